// round 7
// baseline (speedup 1.0000x reference)
#include <cuda_runtime.h>

#define IMG    512
#define OUTD   502
#define NIMG   96
#define TILE_W 86
#define VCOLS  96
#define TILE_H 16
#define RCHUNK 8
#define GBX    6
#define GBY    32
#define NBLK   (GBX * GBY * NIMG)   // 18432
#define SROW   104                   // bank-conflict-free for u64+f32 planes (verified mod16/mod32)
#define G      11                    // phase-2 outputs per thread

// Gaussian(sigma=1.5, K=11) normalized weights
#define W0 0.00102839f
#define W1 0.00759864f
#define W2 0.03600077f
#define W3 0.10936070f
#define W4 0.21300553f
#define W5 0.26601172f

typedef unsigned long long u64;

// ---- packed f32x2 helpers (sm_100+) ----
#define PACK2(out, lo, hi) asm("mov.b64 %0, {%1, %2};" : "=l"(out) : "f"(lo), "f"(hi))
#define UNPACK2(lo, hi, in) asm("mov.b64 {%0, %1}, %2;" : "=f"(lo), "=f"(hi) : "l"(in))
#define FMA2(d, a, b, c) asm("fma.rn.f32x2 %0, %1, %2, %3;" : "=l"(d) : "l"(a), "l"(b), "l"(c))
#define MUL2(d, a, b)    asm("mul.rn.f32x2 %0, %1, %2;" : "=l"(d) : "l"(a), "l"(b))

__device__ int      g_flags[2] = {0, 0};
__device__ unsigned g_count    = 0u;
__device__ float    g_partials[NBLK];

// any(img1 > 128), any(img1 < -0.5)
__global__ void k_flags(const float4* __restrict__ x, int n4) {
    bool f1 = false, f2 = false;
    for (int i = blockIdx.x * blockDim.x + threadIdx.x; i < n4; i += gridDim.x * blockDim.x) {
        float4 v = x[i];
        f1 |= (v.x > 128.0f) | (v.y > 128.0f) | (v.z > 128.0f) | (v.w > 128.0f);
        f2 |= (v.x < -0.5f) | (v.y < -0.5f) | (v.z < -0.5f) | (v.w < -0.5f);
    }
    unsigned m1 = __ballot_sync(0xffffffffu, f1);
    unsigned m2 = __ballot_sync(0xffffffffu, f2);
    if ((threadIdx.x & 31) == 0) {
        if (m1) atomicOr(&g_flags[0], 1);
        if (m2) atomicOr(&g_flags[1], 1);
    }
}

__global__ __launch_bounds__(128, 6)
void k_ssim(const float* __restrict__ img1, const float* __restrict__ img2,
            float* __restrict__ out) {
    __shared__ u64   s01[TILE_H][SROW];   // packed (vconv img1, vconv img2)
    __shared__ u64   s23[TILE_H][SROW];   // packed (vconv img1^2, vconv img2^2)
    __shared__ float s4 [TILE_H][SROW];   // vconv img1*img2
    __shared__ float warpsum[4];
    __shared__ int   s_last;
    __shared__ double red[4];

    const float Wf[11] = {W0, W1, W2, W3, W4, W5, W4, W3, W2, W1, W0};
    u64 w2[6];
    {
        const float wv[6] = {W0, W1, W2, W3, W4, W5};
#pragma unroll
        for (int k = 0; k < 6; k++) PACK2(w2[k], wv[k], wv[k]);
    }
#define WIDX(k) ((k) < 6 ? (k) : 10 - (k))

    const int tid = threadIdx.x;
    const int bx = blockIdx.x, by = blockIdx.y, z = blockIdx.z;
    const float* p1 = img1 + (size_t)z * IMG * IMG;
    const float* p2 = img2 + (size_t)z * IMG * IMG;
    const int ybase = by * TILE_H;

    // ---------------- Phase 1: vertical 11-tap conv, 2 chunks of 8 rows -------------------
    // (chunking halves accumulator live range: 40 regs instead of 80)
    if (tid < VCOLS) {
        const int gx = bx * TILE_W + tid;
        const bool colok = (gx < IMG);

#pragma unroll 1
        for (int c = 0; c < 2; c++) {
            const int rbase = c * RCHUNK;

            u64 acc01[RCHUNK], acc23[RCHUNK];
            float acc4[RCHUNK];
#pragma unroll
            for (int r = 0; r < RCHUNK; r++) { acc01[r] = 0ull; acc23[r] = 0ull; acc4[r] = 0.0f; }

#pragma unroll
            for (int jj = 0; jj < RCHUNK + 10; jj++) {
                const int yin = ybase + rbase + jj;
                float a = 0.0f, b = 0.0f;
                if (colok && yin < IMG) {
                    a = p1[yin * IMG + gx];
                    b = p2[yin * IMG + gx];
                }
                u64 vab, vsq;
                PACK2(vab, a, b);
                MUL2(vsq, vab, vab);
                const float ab = a * b;
#pragma unroll
                for (int r = 0; r < RCHUNK; r++) {
                    const int k = jj - r;
                    if (k >= 0 && k < 11) {
                        FMA2(acc01[r], vab, w2[WIDX(k)], acc01[r]);
                        FMA2(acc23[r], vsq, w2[WIDX(k)], acc23[r]);
                        acc4[r] = fmaf(Wf[k], ab, acc4[r]);
                    }
                }
            }

#pragma unroll
            for (int r = 0; r < RCHUNK; r++) {
                s01[rbase + r][tid] = acc01[r];
                s23[rbase + r][tid] = acc23[r];
                s4 [rbase + r][tid] = acc4[r];
            }
        }
    }
    __syncthreads();

    // ---------------- Phase 2: horizontal 11-tap conv, 11 outputs per thread --------------
    const int y  = tid >> 3;      // 0..15 output row
    const int cg = tid & 7;       // 0..7  column group
    const int xs = cg * G;        // local out cols xs..xs+10 (reads to xs+20 <= 97 < SROW)

    u64 o01[G], o23[G];
    float o4[G];
#pragma unroll
    for (int s = 0; s < G; s++) { o01[s] = 0ull; o23[s] = 0ull; o4[s] = 0.0f; }

    {
        const u64* r01 = &s01[y][xs];
#pragma unroll
        for (int i = 0; i < 21; i++) {
            const u64 v = r01[i];
#pragma unroll
            for (int s = 0; s < G; s++) {
                const int k = i - s;
                if (k >= 0 && k < 11) FMA2(o01[s], v, w2[WIDX(k)], o01[s]);
            }
        }
    }
    {
        const u64* r23 = &s23[y][xs];
#pragma unroll
        for (int i = 0; i < 21; i++) {
            const u64 v = r23[i];
#pragma unroll
            for (int s = 0; s < G; s++) {
                const int k = i - s;
                if (k >= 0 && k < 11) FMA2(o23[s], v, w2[WIDX(k)], o23[s]);
            }
        }
    }
    {
        const float* r4 = &s4[y][xs];
#pragma unroll
        for (int i = 0; i < 21; i++) {
            const float v = r4[i];
#pragma unroll
            for (int s = 0; s < G; s++) {
                const int k = i - s;
                if (k >= 0 && k < 11) o4[s] = fmaf(Wf[k], v, o4[s]);
            }
        }
    }

    // ---------------- SSIM map + block-local sum ----------------
    const float maxv = g_flags[0] ? 255.0f : 1.0f;
    const float minv = g_flags[1] ? -1.0f : 0.0f;
    const float L  = maxv - minv;
    const float C1 = (0.01f * L) * (0.01f * L);
    const float C2 = (0.03f * L) * (0.03f * L);

    const int gy   = ybase + y;
    const int xlim = min(TILE_W, OUTD - bx * TILE_W);

    float lsum = 0.0f;
    if (gy < OUTD) {
#pragma unroll
        for (int s = 0; s < G; s++) {
            const int x = xs + s;
            if (x < xlim) {
                float mu1, mu2, e11, e22;
                UNPACK2(mu1, mu2, o01[s]);
                UNPACK2(e11, e22, o23[s]);
                const float mu1s = mu1 * mu1, mu2s = mu2 * mu2, mu12 = mu1 * mu2;
                const float s1  = e11 - mu1s;
                const float s2  = e22 - mu2s;
                const float s12 = o4[s] - mu12;
                const float num = (2.0f * mu12 + C1) * (2.0f * s12 + C2);
                const float den = (mu1s + mu2s + C1) * (s1 + s2 + C2);
                lsum += __fdividef(num, den);
            }
        }
    }

#pragma unroll
    for (int off = 16; off > 0; off >>= 1)
        lsum += __shfl_down_sync(0xffffffffu, lsum, off);

    if ((tid & 31) == 0) warpsum[tid >> 5] = lsum;
    __syncthreads();

    const int bid = bx + GBX * (by + GBY * z);
    if (tid == 0) {
        g_partials[bid] = warpsum[0] + warpsum[1] + warpsum[2] + warpsum[3];
        __threadfence();
        unsigned v = atomicAdd(&g_count, 1u);
        s_last = (v == NBLK - 1) ? 1 : 0;
    }
    __syncthreads();

    // ---------------- last block: final reduction + state reset ----------------
    if (s_last) {
        double s = 0.0;
        const int per = NBLK / 128;  // 144
#pragma unroll 4
        for (int i = 0; i < per; i++)
            s += (double)__ldcg(&g_partials[tid * per + i]);
#pragma unroll
        for (int off = 16; off > 0; off >>= 1)
            s += __shfl_down_sync(0xffffffffu, s, off);
        if ((tid & 31) == 0) red[tid >> 5] = s;
        __syncthreads();
        if (tid == 0) {
            const double cnt = (double)NIMG * OUTD * OUTD;
            out[0] = (float)(1.0 - (red[0] + red[1] + red[2] + red[3]) / cnt);
            g_flags[0] = 0;
            g_flags[1] = 0;
            g_count    = 0u;
        }
    }
}

extern "C" void kernel_launch(void* const* d_in, const int* in_sizes, int n_in,
                              void* d_out, int out_size) {
    const float* img1 = (const float*)d_in[0];
    const float* img2 = (const float*)d_in[1];
    float* out = (float*)d_out;

    k_flags<<<2048, 256>>>((const float4*)img1, (IMG * IMG * NIMG) / 4);
    dim3 grid(GBX, GBY, NIMG);
    k_ssim<<<grid, 128>>>(img1, img2, out);
}